// round 4
// baseline (speedup 1.0000x reference)
#include <cuda_runtime.h>
#include <cstdint>
#include <cstddef>

typedef unsigned long long u64;

// ---------------------------------------------------------------------------
// Scratch (device globals — no allocation allowed)
// ---------------------------------------------------------------------------
__device__ float g_noise[(size_t)1024 * 131072];   // 512 MiB prescaled gumbel noise
__device__ float g_h1[64 * 8192];
__device__ float g_h2[64 * 8192];
__device__ float g_mask0[64 * 2048];
__device__ float g_p2[(size_t)2 * 64 * 8192];      // K-split partials (gemm1/gemm2)
__device__ float g_p3[(size_t)8 * 64 * 2048];      // gemm3 K-split partials
__device__ uint2 g_keys[1024];
__device__ int   g_icnt[1024];                     // per-iteration noise arrivals

// ---------------------------------------------------------------------------
// f32x2 packed math (Blackwell FFMA2 via PTX)
// ---------------------------------------------------------------------------
#define FMA2(acc, a2, b2) asm("fma.rn.f32x2 %0, %1, %2, %0;" : "+l"(acc) : "l"(a2), "l"(b2))
#define PK2(d, lo, hi)    asm("mov.b64 %0, {%1, %2};" : "=l"(d) : "r"(lo), "r"(hi))
#define UPK2(lo, hi, s)   asm("mov.b64 {%0, %1}, %2;" : "=r"(lo), "=r"(hi) : "l"(s))

// ---------------------------------------------------------------------------
// Threefry-2x32-20 (bit-exact JAX)
// ---------------------------------------------------------------------------
__device__ __forceinline__ void tf_block(uint32_t ks0, uint32_t ks1, uint32_t ks2,
                                         uint32_t x0, uint32_t x1,
                                         uint32_t& o0, uint32_t& o1)
{
    x0 += ks0; x1 += ks1;
#define TFR(r) { x0 += x1; x1 = __funnelshift_l(x1, x1, (r)); x1 ^= x0; }
    TFR(13); TFR(15); TFR(26); TFR(6);
    x0 += ks1; x1 += ks2 + 1u;
    TFR(17); TFR(29); TFR(16); TFR(24);
    x0 += ks2; x1 += ks0 + 2u;
    TFR(13); TFR(15); TFR(26); TFR(6);
    x0 += ks0; x1 += ks1 + 3u;
    TFR(17); TFR(29); TFR(16); TFR(24);
    x0 += ks1; x1 += ks2 + 4u;
    TFR(13); TFR(15); TFR(26); TFR(6);
    x0 += ks2; x1 += ks0 + 5u;
#undef TFR
    o0 = x0; o1 = x1;
}

// per-iteration folded keys + reset arrival counters
__global__ void keys_kernel()
{
    int i = threadIdx.x;
    g_icnt[i] = 0;
    uint32_t k1 = 0u, k2 = 42u;
    uint32_t o0, o1;
    tf_block(k1, k2, k1 ^ k2 ^ 0x1BD11BDAu, 0u, (uint32_t)i, o0, o1);
    g_keys[i] = make_uint2(o0, o1);
}

// bits -> n = -2*log2(-ln u)  so the iter loop is e = 2^(mask*C + n), C = 2*log2(e)
__device__ __forceinline__ float bits_to_noise(uint32_t bits)
{
    uint32_t mant = bits >> 9;
    float fl = __uint2float_rn(mant) * 1.1920928955078125e-07f;  // exact m*2^-23
    float L;
    float d = 1.0f - fl;                                         // exact for fl >= 0.5
    if (d <= 0.015625f) {
        L = d * (1.0f + d * (0.5f + d * (0.3333333432674408f + d * 0.25f)));
    } else if (mant == 0u) {
        L = 87.336544750553109f;                                 // -ln(2^-126)
    } else {
        L = -0.69314718055994531f * __log2f(fl);
    }
    return -2.0f * __log2f(L);
}

// One noise block = 2048 elements of iteration i = b>>6, chunk = b&63.
// Whole CTA cooperates; signals completion on g_icnt[i].
template <int TPB>
__device__ __forceinline__ void noise_body(int b)
{
    const int i = b >> 6;
    const uint2 key = g_keys[i];
    const uint32_t k1 = key.x, k2 = key.y;
    const uint32_t ks2 = k1 ^ k2 ^ 0x1BD11BDAu;
    const uint32_t jbase = (uint32_t)(b & 63) * 2048u + threadIdx.x;
    float* out = g_noise + (size_t)i * 131072u;
#pragma unroll 4
    for (int t = 0; t < 2048 / TPB; t++) {
        uint32_t j = jbase + (uint32_t)t * TPB;
        uint32_t o0, o1;
        tf_block(k1, k2, ks2, 0u, j, o0, o1);
        out[j] = bits_to_noise(o0 ^ o1);
    }
    __syncthreads();
    if (threadIdx.x == 0) {
        __threadfence();
        atomicAdd(&g_icnt[i], 1);
    }
}

// ---------------------------------------------------------------------------
// FFMA2 GEMM: 64 x N fp32, 64x128 tile/CTA, 128 threads, 8x8 per thread with
// paired-column u64 accumulators. K-split -> raw partials. Extra CTAs = noise.
// ---------------------------------------------------------------------------
template <int COLTILES, int KSPLIT>
__global__ __launch_bounds__(128) void gemm_noise(const float* __restrict__ X,
                                                  const float* __restrict__ W,
                                                  float* __restrict__ P,
                                                  int K, int N, int noiseBase)
{
    constexpr int GC = COLTILES * KSPLIT;
    if (blockIdx.x >= GC) { noise_body<128>(noiseBase + (int)blockIdx.x - GC); return; }

    __shared__ float Xs[2][16 * 68];    // [kk][m], padded stride 68
    __shared__ float Ws[2][16 * 132];   // [kk][n], padded stride 132

    const int tid = threadIdx.x;
    const int tx = tid & 15;            // n-group (16 x 8 cols)
    const int ty = tid >> 4;            // m-group (8 x 8 rows)
    const int col = blockIdx.x % COLTILES;
    const int kc  = blockIdx.x / COLTILES;
    const int cb  = col * 128;
    const int Kc  = K / KSPLIT;

    const int xrow = tid >> 1, xkq = (tid & 1) << 3;
    const int wkk  = tid >> 3, wn0 = (tid & 7) << 4;

    const float* Xg = X + (size_t)xrow * K + (size_t)kc * Kc + xkq;
    const float* Wg = W + (size_t)((size_t)kc * Kc + wkk) * N + cb + wn0;

    u64 acc[8][4];
#pragma unroll
    for (int i = 0; i < 8; i++)
#pragma unroll
        for (int j = 0; j < 4; j++) acc[i][j] = 0ull;

    float4 xa0, xa1, wa0, wa1, wa2, wa3;
    xa0 = *(const float4*)(Xg);
    xa1 = *(const float4*)(Xg + 4);
    wa0 = *(const float4*)(Wg);
    wa1 = *(const float4*)(Wg + 4);
    wa2 = *(const float4*)(Wg + 8);
    wa3 = *(const float4*)(Wg + 12);

    {
        Xs[0][(xkq + 0) * 68 + xrow] = xa0.x;
        Xs[0][(xkq + 1) * 68 + xrow] = xa0.y;
        Xs[0][(xkq + 2) * 68 + xrow] = xa0.z;
        Xs[0][(xkq + 3) * 68 + xrow] = xa0.w;
        Xs[0][(xkq + 4) * 68 + xrow] = xa1.x;
        Xs[0][(xkq + 5) * 68 + xrow] = xa1.y;
        Xs[0][(xkq + 6) * 68 + xrow] = xa1.z;
        Xs[0][(xkq + 7) * 68 + xrow] = xa1.w;
        *(float4*)&Ws[0][wkk * 132 + wn0 + 0]  = wa0;
        *(float4*)&Ws[0][wkk * 132 + wn0 + 4]  = wa1;
        *(float4*)&Ws[0][wkk * 132 + wn0 + 8]  = wa2;
        *(float4*)&Ws[0][wkk * 132 + wn0 + 12] = wa3;
    }
    __syncthreads();

    const int nt = Kc >> 4;
    int buf = 0;
    for (int t = 0; t < nt; t++) {
        const bool more = (t + 1 < nt);
        if (more) {
            const float* xg = Xg + (t + 1) * 16;
            const float* wg = Wg + (size_t)(t + 1) * 16 * N;
            xa0 = *(const float4*)(xg);
            xa1 = *(const float4*)(xg + 4);
            wa0 = *(const float4*)(wg);
            wa1 = *(const float4*)(wg + 4);
            wa2 = *(const float4*)(wg + 8);
            wa3 = *(const float4*)(wg + 12);
        }
#pragma unroll
        for (int kk = 0; kk < 16; kk++) {
            const float4 a0 = *(const float4*)&Xs[buf][kk * 68 + ty * 8];
            const float4 a1 = *(const float4*)&Xs[buf][kk * 68 + ty * 8 + 4];
            const float4 b0 = *(const float4*)&Ws[buf][kk * 132 + tx * 8];
            const float4 b1 = *(const float4*)&Ws[buf][kk * 132 + tx * 8 + 4];
            u64 bp[4], ad[8];
            PK2(bp[0], __float_as_uint(b0.x), __float_as_uint(b0.y));
            PK2(bp[1], __float_as_uint(b0.z), __float_as_uint(b0.w));
            PK2(bp[2], __float_as_uint(b1.x), __float_as_uint(b1.y));
            PK2(bp[3], __float_as_uint(b1.z), __float_as_uint(b1.w));
            const float av[8] = {a0.x, a0.y, a0.z, a0.w, a1.x, a1.y, a1.z, a1.w};
#pragma unroll
            for (int i = 0; i < 8; i++) {
                const uint32_t au = __float_as_uint(av[i]);
                PK2(ad[i], au, au);
            }
#pragma unroll
            for (int i = 0; i < 8; i++)
#pragma unroll
                for (int j = 0; j < 4; j++)
                    FMA2(acc[i][j], ad[i], bp[j]);
        }
        if (more) {
            const int nb = buf ^ 1;
            Xs[nb][(xkq + 0) * 68 + xrow] = xa0.x;
            Xs[nb][(xkq + 1) * 68 + xrow] = xa0.y;
            Xs[nb][(xkq + 2) * 68 + xrow] = xa0.z;
            Xs[nb][(xkq + 3) * 68 + xrow] = xa0.w;
            Xs[nb][(xkq + 4) * 68 + xrow] = xa1.x;
            Xs[nb][(xkq + 5) * 68 + xrow] = xa1.y;
            Xs[nb][(xkq + 6) * 68 + xrow] = xa1.z;
            Xs[nb][(xkq + 7) * 68 + xrow] = xa1.w;
            *(float4*)&Ws[nb][wkk * 132 + wn0 + 0]  = wa0;
            *(float4*)&Ws[nb][wkk * 132 + wn0 + 4]  = wa1;
            *(float4*)&Ws[nb][wkk * 132 + wn0 + 8]  = wa2;
            *(float4*)&Ws[nb][wkk * 132 + wn0 + 12] = wa3;
            buf = nb;
        }
        __syncthreads();
    }

    // raw partials: P[kc][m][n]
    float* dst = P + (size_t)kc * 64 * N + (size_t)(ty * 8) * N + cb + tx * 8;
#pragma unroll
    for (int r = 0; r < 8; r++) {
        uint32_t f0, f1, f2, f3, f4, f5, f6, f7;
        UPK2(f0, f1, acc[r][0]);
        UPK2(f2, f3, acc[r][1]);
        UPK2(f4, f5, acc[r][2]);
        UPK2(f6, f7, acc[r][3]);
        float4 o0 = make_float4(__uint_as_float(f0), __uint_as_float(f1),
                                __uint_as_float(f2), __uint_as_float(f3));
        float4 o1 = make_float4(__uint_as_float(f4), __uint_as_float(f5),
                                __uint_as_float(f6), __uint_as_float(f7));
        *(float4*)(dst + (size_t)r * N)     = o0;
        *(float4*)(dst + (size_t)r * N + 4) = o1;
    }
}

// ---------------------------------------------------------------------------
// K-split reduce + bias + batch-BN (+ affine + ReLU). Extra CTAs = noise.
// ---------------------------------------------------------------------------
template <bool AR, int S, int RED>
__global__ __launch_bounds__(256) void reduce_noise(const float* __restrict__ P,
                                                    const float* __restrict__ bias,
                                                    const float* __restrict__ gamma,
                                                    const float* __restrict__ beta,
                                                    float* __restrict__ Y, int N,
                                                    int noiseBase)
{
    if (blockIdx.x >= RED) { noise_body<256>(noiseBase + (int)blockIdx.x - RED); return; }

    const int c = blockIdx.x * 256 + threadIdx.x;
    const float b = bias[c];
    float s = 0.f, ss = 0.f;
#pragma unroll 4
    for (int r = 0; r < 64; r++) {
        float v = b;
#pragma unroll
        for (int q = 0; q < S; q++) v += P[((size_t)q * 64 + r) * N + c];
        s += v; ss += v * v;
    }
    const float mean = s * 0.015625f;
    const float inv  = rsqrtf(fmaf(-mean, mean, ss * 0.015625f) + 1e-5f);
    const float ga = AR ? gamma[c] : 1.0f;
    const float be = AR ? beta[c]  : 0.0f;
#pragma unroll 4
    for (int r = 0; r < 64; r++) {
        float v = b;
#pragma unroll
        for (int q = 0; q < S; q++) v += P[((size_t)q * 64 + r) * N + c];
        float y = (v - mean) * inv;
        if (AR) y = fmaxf(fmaf(y, ga, be), 0.0f);
        Y[(size_t)r * N + c] = y;
    }
}

// ---------------------------------------------------------------------------
// Iteration kernel fused with residual noise generation.
// blockIdx 0..63 = row chains (512 thr, 4 cols/thread); rest = noise CTAs.
// Rows spin on g_icnt readiness (16-ahead window, polled every 8 iters).
// ---------------------------------------------------------------------------
__device__ __forceinline__ float ex2f(float x)
{
    float y; asm("ex2.approx.f32 %0, %1;" : "=f"(y) : "f"(x)); return y;
}

__global__ __launch_bounds__(512) void iter_noise(float* __restrict__ zout, int noiseBase)
{
    if (blockIdx.x >= 64) { noise_body<512>(noiseBase + (int)blockIdx.x - 64); return; }

    const int row  = blockIdx.x;
    const int tid  = threadIdx.x;
    const int lane = tid & 31, wid = tid >> 5;
    const float C = 2.8853900817779268f;   // 2*log2(e)

    float4 m = *(const float4*)(g_mask0 + row * 2048 + 4 * tid);
    float4 z = make_float4(0.f, 0.f, 0.f, 0.f);

    __shared__ float wsum[2][16];
    volatile int* icnt = (volatile int*)g_icnt;

    const float4* np = (const float4*)g_noise + (size_t)row * 512 + tid;

    // ensure iterations 0..16 ready before the pipeline starts
    if (tid == 0) {
        for (int w = 0; w <= 16; w++)
            while (icnt[w] < 64) {}
        __threadfence();
    }
    __syncthreads();

    float4 nx = np[0];
    for (int i = 0; i < 1024; i++) {
        const float4 cur = nx;
        if (i < 1023) nx = np[(size_t)(i + 1) * 32768];

        const float e0 = ex2f(fmaf(m.x, C, cur.x));
        const float e1 = ex2f(fmaf(m.y, C, cur.y));
        const float e2 = ex2f(fmaf(m.z, C, cur.z));
        const float e3 = ex2f(fmaf(m.w, C, cur.w));
        float s = (e0 + e1) + (e2 + e3);
#pragma unroll
        for (int o = 16; o; o >>= 1) s += __shfl_xor_sync(0xffffffffu, s, o);
        if (lane == 0) wsum[i & 1][wid] = s;

        if (tid == 0 && (i & 7) == 0) {   // readiness window: up to i+16
            const int wend = (i + 16 < 1023) ? i + 16 : 1023;
            for (int w = i + 1; w <= wend; w++)
                while (icnt[w] < 64) {}
            __threadfence();
        }
        __syncthreads();

        float t = wsum[i & 1][lane & 15];
#pragma unroll
        for (int o = 8; o; o >>= 1) t += __shfl_xor_sync(0xffffffffu, t, o);
        float r; asm("rcp.approx.f32 %0, %1;" : "=f"(r) : "f"(t));
        m.x = e0 * r; m.y = e1 * r; m.z = e2 * r; m.w = e3 * r;
        z.x = fmaxf(z.x, m.x); z.y = fmaxf(z.y, m.y);
        z.z = fmaxf(z.z, m.z); z.w = fmaxf(z.w, m.w);
    }
    *(float4*)(zout + row * 2048 + 4 * tid) = z;
}

// ---------------------------------------------------------------------------
// Launch
// ---------------------------------------------------------------------------
extern "C" void kernel_launch(void* const* d_in, const int* in_sizes, int n_in,
                              void* d_out, int out_size)
{
    const float* f   = (const float*)d_in[0];
    const float* W1  = (const float*)d_in[1];
    const float* b1  = (const float*)d_in[2];
    const float* g1  = (const float*)d_in[3];
    const float* be1 = (const float*)d_in[4];
    const float* W2  = (const float*)d_in[5];
    const float* b2  = (const float*)d_in[6];
    const float* g2  = (const float*)d_in[7];
    const float* be2 = (const float*)d_in[8];
    const float* W3  = (const float*)d_in[9];
    const float* b3  = (const float*)d_in[10];
    float* out = (float*)d_out;

    void *p1, *p2, *p3, *pp2, *pp3;
    cudaGetSymbolAddress(&p1, g_h1);
    cudaGetSymbolAddress(&p2, g_h2);
    cudaGetSymbolAddress(&p3, g_mask0);
    cudaGetSymbolAddress(&pp2, g_p2);
    cudaGetSymbolAddress(&pp3, g_p3);
    float* h1 = (float*)p1;
    float* h2 = (float*)p2;
    float* mk = (float*)p3;
    float* q2 = (float*)pp2;
    float* q3 = (float*)pp3;

    // noise block assignment (65536 total), in iteration order
    constexpr int NZ_G1 = 2048;   // base 0
    constexpr int NZ_R1 = 1536;   // base 2048
    constexpr int NZ_G2 = 7168;   // base 3584
    constexpr int NZ_R2 = 1536;   // base 10752
    constexpr int NZ_G3 = 2048;   // base 12288
    constexpr int NZ_R3 = 512;    // base 14336
    constexpr int NZ_IT = 65536 - 14848;   // base 14848

    keys_kernel<<<1, 1024>>>();

    gemm_noise<64, 2><<<128 + NZ_G1, 128>>>(f,  W1, q2, 2048, 8192, 0);
    reduce_noise<true, 2, 32><<<32 + NZ_R1, 256>>>(q2, b1, g1, be1, h1, 8192, 2048);

    gemm_noise<64, 2><<<128 + NZ_G2, 128>>>(h1, W2, q2, 8192, 8192, 3584);
    reduce_noise<true, 2, 32><<<32 + NZ_R2, 256>>>(q2, b2, g2, be2, h2, 8192, 10752);

    gemm_noise<16, 8><<<128 + NZ_G3, 128>>>(h2, W3, q3, 8192, 2048, 12288);
    reduce_noise<false, 8, 8><<<8 + NZ_R3, 256>>>(q3, b3, nullptr, nullptr, mk, 2048, 14336);

    iter_noise<<<64 + NZ_IT, 512>>>(out, 14848);
}

// round 5
// speedup vs baseline: 1.3377x; 1.3377x over previous
#include <cuda_runtime.h>
#include <cstdint>
#include <cstddef>

// ---------------------------------------------------------------------------
// Scratch (device globals — no allocation allowed)
// ---------------------------------------------------------------------------
__device__ float g_noise[(size_t)1024 * 131072];   // 512 MiB prescaled gumbel noise
__device__ float g_h1[64 * 8192];
__device__ float g_h2[64 * 8192];
__device__ float g_mask0[64 * 2048];
__device__ float g_p2[(size_t)4 * 64 * 8192];      // K-split partials (g1 x2 / g2 x4)
__device__ float g_p3[(size_t)8 * 64 * 2048];      // gemm3 K-split x8 partials
__device__ uint2 g_keys[1024];
__device__ int   g_icnt[1024];                     // per-iteration noise arrivals

// ---------------------------------------------------------------------------
// Threefry-2x32-20 (bit-exact JAX)
// ---------------------------------------------------------------------------
__device__ __forceinline__ void tf_block(uint32_t ks0, uint32_t ks1, uint32_t ks2,
                                         uint32_t x0, uint32_t x1,
                                         uint32_t& o0, uint32_t& o1)
{
    x0 += ks0; x1 += ks1;
#define TFR(r) { x0 += x1; x1 = __funnelshift_l(x1, x1, (r)); x1 ^= x0; }
    TFR(13); TFR(15); TFR(26); TFR(6);
    x0 += ks1; x1 += ks2 + 1u;
    TFR(17); TFR(29); TFR(16); TFR(24);
    x0 += ks2; x1 += ks0 + 2u;
    TFR(13); TFR(15); TFR(26); TFR(6);
    x0 += ks0; x1 += ks1 + 3u;
    TFR(17); TFR(29); TFR(16); TFR(24);
    x0 += ks1; x1 += ks2 + 4u;
    TFR(13); TFR(15); TFR(26); TFR(6);
    x0 += ks2; x1 += ks0 + 5u;
#undef TFR
    o0 = x0; o1 = x1;
}

// per-iteration folded keys + reset arrival counters (runs first every replay)
__global__ void keys_kernel()
{
    int i = threadIdx.x;
    g_icnt[i] = 0;
    uint32_t k1 = 0u, k2 = 42u;
    uint32_t o0, o1;
    tf_block(k1, k2, k1 ^ k2 ^ 0x1BD11BDAu, 0u, (uint32_t)i, o0, o1);
    g_keys[i] = make_uint2(o0, o1);
}

// bits -> n = -2*log2(-ln u)  so the iter loop is e = 2^(mask*C + n), C = 2*log2(e)
__device__ __forceinline__ float bits_to_noise(uint32_t bits)
{
    uint32_t mant = bits >> 9;
    float fl = __uint2float_rn(mant) * 1.1920928955078125e-07f;  // exact m*2^-23
    float L;
    float d = 1.0f - fl;                                         // exact for fl >= 0.5
    if (d <= 0.015625f) {
        L = d * (1.0f + d * (0.5f + d * (0.3333333432674408f + d * 0.25f)));
    } else if (mant == 0u) {
        L = 87.336544750553109f;                                 // -ln(2^-126)
    } else {
        L = -0.69314718055994531f * __log2f(fl);
    }
    return -2.0f * __log2f(L);
}

// One noise block = 2048 elements of iteration i = b>>6, chunk = b&63.
template <int TPB>
__device__ __forceinline__ void noise_body(int b)
{
    const int i = b >> 6;
    const uint2 key = g_keys[i];
    const uint32_t k1 = key.x, k2 = key.y;
    const uint32_t ks2 = k1 ^ k2 ^ 0x1BD11BDAu;
    const uint32_t jbase = (uint32_t)(b & 63) * 2048u + threadIdx.x;
    float* out = g_noise + (size_t)i * 131072u;
#pragma unroll 4
    for (int t = 0; t < 2048 / TPB; t++) {
        uint32_t j = jbase + (uint32_t)t * TPB;
        uint32_t o0, o1;
        tf_block(k1, k2, ks2, 0u, j, o0, o1);
        out[j] = bits_to_noise(o0 ^ o1);
    }
    __syncthreads();
    if (threadIdx.x == 0) {
        __threadfence();
        atomicAdd(&g_icnt[i], 1);
    }
}

// ---------------------------------------------------------------------------
// Scalar GEMM: 64 x N fp32, 64x64 tile/CTA, 256 threads, 4x4/thread,
// double-buffered smem, K-split -> raw partials. Extra CTAs generate noise.
// ---------------------------------------------------------------------------
template <int COLTILES, int KSPLIT>
__global__ __launch_bounds__(256) void gemm_noise(const float* __restrict__ X,
                                                  const float* __restrict__ W,
                                                  float* __restrict__ P,
                                                  int K, int N, int noiseBase)
{
    constexpr int GC = COLTILES * KSPLIT;
    if (blockIdx.x >= GC) { noise_body<256>(noiseBase + (int)blockIdx.x - GC); return; }

    __shared__ float Xs[2][1024];   // [kk][m]
    __shared__ float Ws[2][1024];   // [kk][n]

    const int tid = threadIdx.x;
    const int tx = tid & 15, ty = tid >> 4;
    const int col = blockIdx.x % COLTILES;
    const int kc  = blockIdx.x / COLTILES;
    const int cb  = col * 64;
    const int Kc  = K / KSPLIT;
    const int k0  = kc * Kc;

    const int lm = tid >> 2;
    const int lk = (tid & 3) << 2;
    const int wk = tid >> 4;
    const int wn = (tid & 15) << 2;

    float acc[4][4] = {};

    float4 xa = *reinterpret_cast<const float4*>(X + (size_t)lm * K + k0 + lk);
    float4 wa = *reinterpret_cast<const float4*>(W + (size_t)(k0 + wk) * N + cb + wn);
    Xs[0][(lk + 0) * 64 + lm] = xa.x;
    Xs[0][(lk + 1) * 64 + lm] = xa.y;
    Xs[0][(lk + 2) * 64 + lm] = xa.z;
    Xs[0][(lk + 3) * 64 + lm] = xa.w;
    *reinterpret_cast<float4*>(&Ws[0][wk * 64 + wn]) = wa;
    __syncthreads();

    const int nt = Kc >> 4;
    int buf = 0;
    for (int t = 0; t < nt; t++) {
        float4 xn, wn4;
        const bool more = (t + 1 < nt);
        if (more) {
            int kk0 = k0 + ((t + 1) << 4);
            xn  = *reinterpret_cast<const float4*>(X + (size_t)lm * K + kk0 + lk);
            wn4 = *reinterpret_cast<const float4*>(W + (size_t)(kk0 + wk) * N + cb + wn);
        }
#pragma unroll
        for (int kk = 0; kk < 16; kk++) {
            const float4 a4 = *reinterpret_cast<const float4*>(&Xs[buf][(kk << 6) + (ty << 2)]);
            const float4 b4 = *reinterpret_cast<const float4*>(&Ws[buf][(kk << 6) + (tx << 2)]);
            const float av[4] = {a4.x, a4.y, a4.z, a4.w};
            const float bv[4] = {b4.x, b4.y, b4.z, b4.w};
#pragma unroll
            for (int i2 = 0; i2 < 4; i2++)
#pragma unroll
                for (int j2 = 0; j2 < 4; j2++)
                    acc[i2][j2] = fmaf(av[i2], bv[j2], acc[i2][j2]);
        }
        if (more) {
            const int nb = buf ^ 1;
            Xs[nb][(lk + 0) * 64 + lm] = xn.x;
            Xs[nb][(lk + 1) * 64 + lm] = xn.y;
            Xs[nb][(lk + 2) * 64 + lm] = xn.z;
            Xs[nb][(lk + 3) * 64 + lm] = xn.w;
            *reinterpret_cast<float4*>(&Ws[nb][wk * 64 + wn]) = wn4;
            buf = nb;
        }
        __syncthreads();
    }

    // raw partials: P[kc][m][n]
    float* dst = P + (size_t)kc * 64 * N;
#pragma unroll
    for (int i = 0; i < 4; i++) {
        float4 o = make_float4(acc[i][0], acc[i][1], acc[i][2], acc[i][3]);
        *reinterpret_cast<float4*>(dst + (size_t)((ty << 2) + i) * N + cb + (tx << 2)) = o;
    }
}

// ---------------------------------------------------------------------------
// K-split reduce + bias + batch-BN (+ affine + ReLU). Extra CTAs = noise.
// ---------------------------------------------------------------------------
template <bool AR, int S, int RED>
__global__ __launch_bounds__(256) void reduce_noise(const float* __restrict__ P,
                                                    const float* __restrict__ bias,
                                                    const float* __restrict__ gamma,
                                                    const float* __restrict__ beta,
                                                    float* __restrict__ Y, int N,
                                                    int noiseBase)
{
    if (blockIdx.x >= RED) { noise_body<256>(noiseBase + (int)blockIdx.x - RED); return; }

    const int c = blockIdx.x * 256 + threadIdx.x;
    const float b = bias[c];
    float s = 0.f, ss = 0.f;
#pragma unroll 4
    for (int r = 0; r < 64; r++) {
        float v = b;
#pragma unroll
        for (int q = 0; q < S; q++) v += P[((size_t)q * 64 + r) * N + c];
        s += v; ss += v * v;
    }
    const float mean = s * 0.015625f;
    const float inv  = rsqrtf(fmaf(-mean, mean, ss * 0.015625f) + 1e-5f);
    const float ga = AR ? gamma[c] : 1.0f;
    const float be = AR ? beta[c]  : 0.0f;
#pragma unroll 4
    for (int r = 0; r < 64; r++) {
        float v = b;
#pragma unroll
        for (int q = 0; q < S; q++) v += P[((size_t)q * 64 + r) * N + c];
        float y = (v - mean) * inv;
        if (AR) y = fmaxf(fmaf(y, ga, be), 0.0f);
        Y[(size_t)r * N + c] = y;
    }
}

// ---------------------------------------------------------------------------
// Iteration kernel (+ small noise tail for iterations 928..1023).
// blockIdx 0..63 = row chains (512 thr, 4 cols/thread).
// ---------------------------------------------------------------------------
__device__ __forceinline__ float ex2f(float x)
{
    float y; asm("ex2.approx.f32 %0, %1;" : "=f"(y) : "f"(x)); return y;
}

__global__ __launch_bounds__(512) void iter_noise(float* __restrict__ zout, int noiseBase)
{
    if (blockIdx.x >= 64) { noise_body<512>(noiseBase + (int)blockIdx.x - 64); return; }

    const int row  = blockIdx.x;
    const int tid  = threadIdx.x;
    const int lane = tid & 31, wid = tid >> 5;
    const float C = 2.8853900817779268f;   // 2*log2(e)

    float4 m = *(const float4*)(g_mask0 + row * 2048 + 4 * tid);
    float4 z = make_float4(0.f, 0.f, 0.f, 0.f);

    __shared__ float wsum[2][16];
    volatile int* icnt = (volatile int*)g_icnt;

    const float4* np = (const float4*)g_noise + (size_t)row * 512 + tid;

    // iterations 0..927 are complete (prior launches); wait for 928..944 window
    if (tid == 0) {
        for (int w = 928; w <= 944; w++)
            while (icnt[w] < 64) {}
        __threadfence();
    }
    __syncthreads();

    float4 nx = np[0];
    for (int i = 0; i < 1024; i++) {
        const float4 cur = nx;
        if (i < 1023) nx = np[(size_t)(i + 1) * 32768];

        const float e0 = ex2f(fmaf(m.x, C, cur.x));
        const float e1 = ex2f(fmaf(m.y, C, cur.y));
        const float e2 = ex2f(fmaf(m.z, C, cur.z));
        const float e3 = ex2f(fmaf(m.w, C, cur.w));
        float s = (e0 + e1) + (e2 + e3);
#pragma unroll
        for (int o = 16; o; o >>= 1) s += __shfl_xor_sync(0xffffffffu, s, o);
        if (lane == 0) wsum[i & 1][wid] = s;

        // readiness window for the in-flight noise tail (only matters i>=912)
        if (tid == 0 && (i & 7) == 0 && i >= 912) {
            const int wend = (i + 16 < 1023) ? i + 16 : 1023;
            for (int w = i + 1; w <= wend; w++)
                while (icnt[w] < 64) {}
            __threadfence();
        }
        __syncthreads();

        const float4* wp = (const float4*)wsum[i & 1];
        const float4 t0 = wp[0], t1 = wp[1], t2 = wp[2], t3 = wp[3];
        const float t = (((t0.x + t0.y) + (t0.z + t0.w)) + ((t1.x + t1.y) + (t1.z + t1.w)))
                      + (((t2.x + t2.y) + (t2.z + t2.w)) + ((t3.x + t3.y) + (t3.z + t3.w)));
        float r; asm("rcp.approx.f32 %0, %1;" : "=f"(r) : "f"(t));
        m.x = e0 * r; m.y = e1 * r; m.z = e2 * r; m.w = e3 * r;
        z.x = fmaxf(z.x, m.x); z.y = fmaxf(z.y, m.y);
        z.z = fmaxf(z.z, m.z); z.w = fmaxf(z.w, m.w);
    }
    *(float4*)(zout + row * 2048 + 4 * tid) = z;
}

// ---------------------------------------------------------------------------
// Launch
// ---------------------------------------------------------------------------
extern "C" void kernel_launch(void* const* d_in, const int* in_sizes, int n_in,
                              void* d_out, int out_size)
{
    const float* f   = (const float*)d_in[0];
    const float* W1  = (const float*)d_in[1];
    const float* b1  = (const float*)d_in[2];
    const float* g1  = (const float*)d_in[3];
    const float* be1 = (const float*)d_in[4];
    const float* W2  = (const float*)d_in[5];
    const float* b2  = (const float*)d_in[6];
    const float* g2  = (const float*)d_in[7];
    const float* be2 = (const float*)d_in[8];
    const float* W3  = (const float*)d_in[9];
    const float* b3  = (const float*)d_in[10];
    float* out = (float*)d_out;

    void *p1, *p2, *p3, *pp2, *pp3;
    cudaGetSymbolAddress(&p1, g_h1);
    cudaGetSymbolAddress(&p2, g_h2);
    cudaGetSymbolAddress(&p3, g_mask0);
    cudaGetSymbolAddress(&pp2, g_p2);
    cudaGetSymbolAddress(&pp3, g_p3);
    float* h1 = (float*)p1;
    float* h2 = (float*)p2;
    float* mk = (float*)p3;
    float* q2 = (float*)pp2;
    float* q3 = (float*)pp3;

    // noise block bases (65536 total, iteration-ordered):
    //   g1: 12288 @0      r1: 2048 @12288   g2: 24576 @14336
    //   r2: 2048 @38912   g3: 14336 @40960  r3: 4096 @55296
    //   iter tail: 6144 @59392 (iterations 928..1023)
    keys_kernel<<<1, 1024>>>();

    gemm_noise<128, 2><<<256 + 12288, 256>>>(f,  W1, q2, 2048, 8192, 0);
    reduce_noise<true, 2, 32><<<32 + 2048, 256>>>(q2, b1, g1, be1, h1, 8192, 12288);

    gemm_noise<128, 4><<<512 + 24576, 256>>>(h1, W2, q2, 8192, 8192, 14336);
    reduce_noise<true, 4, 32><<<32 + 2048, 256>>>(q2, b2, g2, be2, h2, 8192, 38912);

    gemm_noise<32, 8><<<256 + 14336, 256>>>(h2, W3, q3, 8192, 2048, 40960);
    reduce_noise<false, 8, 8><<<8 + 4096, 256>>>(q3, b3, nullptr, nullptr, mk, 2048, 55296);

    iter_noise<<<64 + 6144, 512>>>(out, 59392);
}